// round 8
// baseline (speedup 1.0000x reference)
#include <cuda_runtime.h>
#include <cuda_fp16.h>

#define NUM_USERS 80000
#define NUM_ITEMS 40000
#define NUM_NODES 120000
#define RPN       (NUM_NODES + 1)
#define DIM       64
#define NE        (NUM_NODES * DIM)     // 7,680,000
#define NE4       (NE / 4)              // 1,920,000
#define NU4       (NUM_USERS * DIM / 4) // 1,280,000
#define ALPHA     0.8f
#define MAX_EPATH 2000000

// ---------------- scratch (device globals; zero-initialized .bss) ----------
__device__ __align__(256) __half2 g_hin[NE / 2];  // fp16 [user_emb; item_emb]
__device__ __align__(256) __half2 g_h0[NE / 2];   // e0 (fp16)
__device__ __align__(256) __half2 g_h1[NE / 2];   // e1 (fp16)
__device__ __align__(256) __half2 g_h2[NE / 2];   // e2 (fp16)
__device__ __align__(256) float   g_softv[MAX_EPATH];
__device__ __align__(256) int     g_rp_pos[RPN];
__device__ __align__(256) int     g_rp_neg[RPN];
__device__ __align__(256) int     g_rp_path[RPN];
__device__ __align__(256) float   g_thetaw[8];

// ---------------- fused prologue: cvt fp32->fp16 + theta softmax -----------
__global__ __launch_bounds__(256) void k_prologue(
    const float4* __restrict__ U, const float4* __restrict__ I,
    __half2* __restrict__ H,
    const float* __restrict__ theta, float* __restrict__ tw, int n_theta)
{
    int i = blockIdx.x * blockDim.x + threadIdx.x;
    if (i < NE4) {
        float4 v = (i < NU4) ? U[i] : I[i - NU4];
        H[2 * i]     = __floats2half2_rn(v.x, v.y);
        H[2 * i + 1] = __floats2half2_rn(v.z, v.w);
    }
    if (i == 0) {
        float m = -1e30f;
        for (int k = 0; k < n_theta; k++) m = fmaxf(m, theta[k]);
        float s = 0.f; float w[8];
        for (int k = 0; k < n_theta; k++) { w[k] = expf(theta[k] - m); s += w[k]; }
        for (int k = 0; k < n_theta; k++) tw[k] = w[k] / s;
    }
}

// ---------------- row pointers via binary search (rows sorted) --------------
__device__ __forceinline__ int lb(const int* __restrict__ a, int n, int key)
{
    int lo = 0, hi = n;
    while (lo < hi) {
        int mid = (lo + hi) >> 1;
        if (a[mid] < key) lo = mid + 1; else hi = mid;
    }
    return lo;
}

__global__ __launch_bounds__(256) void k_rowptr(
    const int* __restrict__ pr, int np,
    const int* __restrict__ nr, int nn,
    const int* __restrict__ qr, int nq,
    int* __restrict__ rp_p, int* __restrict__ rp_n, int* __restrict__ rp_q)
{
    int r = blockIdx.x * blockDim.x + threadIdx.x;
    if (r >= RPN) return;
    rp_p[r] = lb(pr, np, r);
    rp_n[r] = lb(nr, nn, r);
    rp_q[r] = lb(qr, nq, r);
}

// ---------------- path edge weights: ev = exp(counts @ theta_w) -------------
__global__ __launch_bounds__(256) void k_path_ev(
    const float* __restrict__ p_counts, const float* __restrict__ tw,
    float* __restrict__ softv, int n)
{
    const int t = blockIdx.x * blockDim.x + threadIdx.x;
    const int e0 = 2 * t;
    if (e0 >= n) return;
    const float w0 = tw[0], w1 = tw[1], w2 = tw[2],
                w3 = tw[3], w4 = tw[4], w5 = tw[5];
    const float4* src = (const float4*)(p_counts + (size_t)e0 * 6);
    float4 a = src[0];
    float4 b = src[1];
    float4 c = src[2];
    float v0 = a.x * w0;
    v0 = fmaf(a.y, w1, v0); v0 = fmaf(a.z, w2, v0);
    v0 = fmaf(a.w, w3, v0); v0 = fmaf(b.x, w4, v0);
    v0 = fmaf(b.y, w5, v0);
    float ev0 = expf(v0);
    if (e0 + 1 < n) {
        float v1 = b.z * w0;
        v1 = fmaf(b.w, w1, v1); v1 = fmaf(c.x, w2, v1);
        v1 = fmaf(c.y, w3, v1); v1 = fmaf(c.z, w4, v1);
        v1 = fmaf(c.w, w5, v1);
        *(float2*)(softv + e0) = make_float2(ev0, expf(v1));
    } else {
        softv[e0] = ev0;
    }
}

// ---------------- strided CSR gather-accumulate (warp-converged) ------------
// Quarter q handles edges b+q, b+q+4, ...; lane owns 8 dims (LDG.128 fp16).
// Trip counts across quarters differ by <=1 -> near-zero divergence.
__device__ __forceinline__ void gather_strided(
    const int* __restrict__ cols, const float* __restrict__ vals,
    int b, int e, float scale, const uint4* __restrict__ X, int q, int ql,
    float acc[8])
{
    int j = b + q;
    if (j >= e) return;
    int   c = __ldg(cols + j);
    float v = __ldg(vals + j);
    uint4 hv = X[(size_t)c * 8 + ql];
    for (; j < e; j += 4) {
        int cn = c; float vn = v; uint4 hvn = hv;
        if (j + 4 < e) {
            cn  = __ldg(cols + j + 4);
            vn  = __ldg(vals + j + 4);
            hvn = X[(size_t)cn * 8 + ql];
        }
        float f = v * scale;
        float2 p0 = __half22float2(*(const __half2*)&hv.x);
        float2 p1 = __half22float2(*(const __half2*)&hv.y);
        float2 p2 = __half22float2(*(const __half2*)&hv.z);
        float2 p3 = __half22float2(*(const __half2*)&hv.w);
        acc[0] = fmaf(f, p0.x, acc[0]); acc[1] = fmaf(f, p0.y, acc[1]);
        acc[2] = fmaf(f, p1.x, acc[2]); acc[3] = fmaf(f, p1.y, acc[3]);
        acc[4] = fmaf(f, p2.x, acc[4]); acc[5] = fmaf(f, p2.y, acc[5]);
        acc[6] = fmaf(f, p3.x, acc[6]); acc[7] = fmaf(f, p3.y, acc[7]);
        c = cn; v = vn; hv = hvn;
    }
}

// combine partial sums across the 4 quarters (lanes ql, ql+8, ql+16, ql+24)
__device__ __forceinline__ void combine4(float acc[8])
{
    #pragma unroll
    for (int k = 0; k < 8; k++) {
        acc[k] += __shfl_xor_sync(0xffffffffu, acc[k], 8);
        acc[k] += __shfl_xor_sync(0xffffffffu, acc[k], 16);
    }
}

__device__ __forceinline__ uint4 pack8(const float acc[8])
{
    uint4 o;
    *(__half2*)&o.x = __floats2half2_rn(acc[0], acc[1]);
    *(__half2*)&o.y = __floats2half2_rn(acc[2], acc[3]);
    *(__half2*)&o.z = __floats2half2_rn(acc[4], acc[5]);
    *(__half2*)&o.w = __floats2half2_rn(acc[6], acc[7]);
    return o;
}

// ---------------- path CSR SpMM (warp per row) -------------------------------
__global__ __launch_bounds__(256) void k_spmm_path_csr(
    const int* __restrict__ rp, const int* __restrict__ cols,
    const float* __restrict__ ev, const uint4* __restrict__ X,
    uint4* __restrict__ H0)
{
    const int lane = threadIdx.x & 31;
    const int r    = blockIdx.x * 8 + (threadIdx.x >> 5);
    if (r >= NUM_NODES) return;
    const int b = __ldg(rp + r), e = __ldg(rp + r + 1);

    // 32-lane strided row sum + butterfly
    float s = 0.f;
    for (int j = b + lane; j < e; j += 32) s += __ldg(ev + j);
    #pragma unroll
    for (int m = 16; m >= 1; m >>= 1)
        s += __shfl_xor_sync(0xffffffffu, s, m);
    const float inv = 1.f / (s + 1e-12f);

    const int q = lane >> 3, ql = lane & 7;
    float acc[8];
    #pragma unroll
    for (int k = 0; k < 8; k++) acc[k] = 0.f;
    gather_strided(cols, ev, b, e, inv, X, q, ql, acc);
    combine4(acc);
    if (lane < 8)
        H0[(size_t)r * 8 + ql] = pack8(acc);
}

// ---------------- fused layer (warp per row): e_new = pos - a*neg + a*e_old --
// FINAL=false: write Hnew fp16. FINAL=true: out = (H0+H1+H2+e_new)/4 fp32.
template<bool FINAL>
__global__ __launch_bounds__(256) void k_layer_csr(
    const int* __restrict__ rp_pos, const int* __restrict__ pcol,
    const float* __restrict__ pval,
    const int* __restrict__ rp_neg, const int* __restrict__ ncol,
    const float* __restrict__ nval,
    const uint4* __restrict__ X,        // gather table == e_old
    const uint4* __restrict__ H0, const uint4* __restrict__ H1,  // FINAL only
    uint4* __restrict__ Hnew, float4* __restrict__ out)
{
    const int lane = threadIdx.x & 31;
    const int r    = blockIdx.x * 8 + (threadIdx.x >> 5);
    if (r >= NUM_NODES) return;
    const int q = lane >> 3, ql = lane & 7;

    float acc[8];
    #pragma unroll
    for (int k = 0; k < 8; k++) acc[k] = 0.f;
    gather_strided(pcol, pval, __ldg(rp_pos + r), __ldg(rp_pos + r + 1),
                   1.0f,  X, q, ql, acc);
    gather_strided(ncol, nval, __ldg(rp_neg + r), __ldg(rp_neg + r + 1),
                   -ALPHA, X, q, ql, acc);
    combine4(acc);

    if (lane >= 8) return;
    const size_t ri = (size_t)r * 8 + ql;
    uint4 ho = X[ri];
    float2 q0 = __half22float2(*(const __half2*)&ho.x);
    float2 q1 = __half22float2(*(const __half2*)&ho.y);
    float2 q2 = __half22float2(*(const __half2*)&ho.z);
    float2 q3 = __half22float2(*(const __half2*)&ho.w);
    float en[8];
    en[0] = fmaf(ALPHA, q0.x, acc[0]); en[1] = fmaf(ALPHA, q0.y, acc[1]);
    en[2] = fmaf(ALPHA, q1.x, acc[2]); en[3] = fmaf(ALPHA, q1.y, acc[3]);
    en[4] = fmaf(ALPHA, q2.x, acc[4]); en[5] = fmaf(ALPHA, q2.y, acc[5]);
    en[6] = fmaf(ALPHA, q3.x, acc[6]); en[7] = fmaf(ALPHA, q3.y, acc[7]);

    if (!FINAL) {
        Hnew[ri] = pack8(en);
    } else {
        uint4 a4 = H0[ri];
        uint4 b4 = H1[ri];
        float2 a0 = __half22float2(*(const __half2*)&a4.x);
        float2 a1 = __half22float2(*(const __half2*)&a4.y);
        float2 a2 = __half22float2(*(const __half2*)&a4.z);
        float2 a3 = __half22float2(*(const __half2*)&a4.w);
        float2 b0 = __half22float2(*(const __half2*)&b4.x);
        float2 b1 = __half22float2(*(const __half2*)&b4.y);
        float2 b2 = __half22float2(*(const __half2*)&b4.z);
        float2 b3 = __half22float2(*(const __half2*)&b4.w);
        float4 o0, o1;
        o0.x = (a0.x + b0.x + q0.x + en[0]) * 0.25f;
        o0.y = (a0.y + b0.y + q0.y + en[1]) * 0.25f;
        o0.z = (a1.x + b1.x + q1.x + en[2]) * 0.25f;
        o0.w = (a1.y + b1.y + q1.y + en[3]) * 0.25f;
        o1.x = (a2.x + b2.x + q2.x + en[4]) * 0.25f;
        o1.y = (a2.y + b2.y + q2.y + en[5]) * 0.25f;
        o1.z = (a3.x + b3.x + q3.x + en[6]) * 0.25f;
        o1.w = (a3.y + b3.y + q3.y + en[7]) * 0.25f;
        out[(size_t)r * 16 + ql * 2]     = o0;
        out[(size_t)r * 16 + ql * 2 + 1] = o1;
    }
}

// ---------------------------------------------------------------------------
extern "C" void kernel_launch(void* const* d_in, const int* in_sizes, int n_in,
                              void* d_out, int out_size)
{
    const float* user_emb = (const float*)d_in[0];
    const float* item_emb = (const float*)d_in[1];
    const float* theta    = (const float*)d_in[2];
    const int*   pos_row  = (const int*)d_in[3];
    const int*   pos_col  = (const int*)d_in[4];
    const float* pos_val  = (const float*)d_in[5];
    const int*   neg_row  = (const int*)d_in[6];
    const int*   neg_col  = (const int*)d_in[7];
    const float* neg_val  = (const float*)d_in[8];
    const int*   p_row    = (const int*)d_in[9];
    const int*   p_col    = (const int*)d_in[10];
    const float* p_counts = (const float*)d_in[11];

    const int n_pos  = in_sizes[3];
    const int n_neg  = in_sizes[6];
    int n_path = in_sizes[9];
    if (n_path > MAX_EPATH) n_path = MAX_EPATH;
    const int n_theta = in_sizes[2] < 8 ? in_sizes[2] : 8;

    float *psv, *ptw;
    int *rpp, *rpn, *rpq;
    __half2 *hin, *h0, *h1, *h2;
    cudaGetSymbolAddress((void**)&hin, g_hin);
    cudaGetSymbolAddress((void**)&h0,  g_h0);
    cudaGetSymbolAddress((void**)&h1,  g_h1);
    cudaGetSymbolAddress((void**)&h2,  g_h2);
    cudaGetSymbolAddress((void**)&psv, g_softv);
    cudaGetSymbolAddress((void**)&rpp, g_rp_pos);
    cudaGetSymbolAddress((void**)&rpn, g_rp_neg);
    cudaGetSymbolAddress((void**)&rpq, g_rp_path);
    cudaGetSymbolAddress((void**)&ptw, g_thetaw);

    const int TB = 256;
    const int row_grid = (NUM_NODES + 7) / 8;     // warp per row, 8 warps/block

    // prologue: fp16 input table + theta softmax
    k_prologue<<<(NE4 + TB - 1) / TB, TB>>>((const float4*)user_emb,
                                            (const float4*)item_emb, hin,
                                            theta, ptw, n_theta);

    // row pointers for all 3 edge lists (rows sorted by construction)
    k_rowptr<<<(RPN + TB - 1) / TB, TB>>>(pos_row, n_pos, neg_row, n_neg,
                                          p_row, n_path, rpp, rpn, rpq);

    // path edge weights ev = exp(counts @ theta_w)
    {
        int pairs = (n_path + 1) / 2;
        k_path_ev<<<(pairs + TB - 1) / TB, TB>>>(p_counts, ptw, psv, n_path);
    }

    // e0: per-row softmax-normalized path gather -> H0
    k_spmm_path_csr<<<row_grid, TB>>>(rpq, p_col, psv, (const uint4*)hin,
                                      (uint4*)h0);

    // layer 1: H1 = pos(H0) - a*neg(H0) + a*H0
    k_layer_csr<false><<<row_grid, TB>>>(rpp, pos_col, pos_val,
                                         rpn, neg_col, neg_val,
                                         (const uint4*)h0, nullptr, nullptr,
                                         (uint4*)h1, nullptr);
    // layer 2
    k_layer_csr<false><<<row_grid, TB>>>(rpp, pos_col, pos_val,
                                         rpn, neg_col, neg_val,
                                         (const uint4*)h1, nullptr, nullptr,
                                         (uint4*)h2, nullptr);
    // layer 3 fused with final mean -> d_out
    k_layer_csr<true><<<row_grid, TB>>>(rpp, pos_col, pos_val,
                                        rpn, neg_col, neg_val,
                                        (const uint4*)h2,
                                        (const uint4*)h0, (const uint4*)h1,
                                        nullptr, (float4*)d_out);
}

// round 9
// speedup vs baseline: 1.1918x; 1.1918x over previous
#include <cuda_runtime.h>
#include <cuda_fp16.h>

#define NUM_USERS 80000
#define NUM_ITEMS 40000
#define NUM_NODES 120000
#define DIM       64
#define NE        (NUM_NODES * DIM)     // 7,680,000
#define NE4       (NE / 4)              // 1,920,000
#define NU4       (NUM_USERS * DIM / 4) // 1,280,000
#define ALPHA     0.8f
#define MAX_EPATH 2000000
#define WEDGES    128                    // edges per warp (proven config)
#define QE        (WEDGES / 4)           // edges per quarter-warp (32)

// ---------------- scratch (device globals; zero-initialized .bss) ----------
__device__ __align__(256) float   g_t[NE];        // fp32 scatter target (zero at entry, restored at exit)
__device__ __align__(256) __half2 g_hin[NE / 2];  // fp16 copy of [user_emb; item_emb]
__device__ __align__(256) __half2 g_h0[NE / 2];   // e0 (fp16)
__device__ __align__(256) __half2 g_h1[NE / 2];   // e1 (fp16)
__device__ __align__(256) __half2 g_h2[NE / 2];   // e2 (fp16)
__device__ __align__(256) float   g_softv[MAX_EPATH];
__device__ __align__(256) float   g_rowsum[NUM_NODES];
__device__ __align__(256) float   g_thetaw[8];

// ---------------- fused prologue: cvt + rowsum zero + theta softmax --------
__global__ __launch_bounds__(256) void k_prologue(
    const float4* __restrict__ U, const float4* __restrict__ I,
    __half2* __restrict__ H, float4* __restrict__ rs4,
    const float* __restrict__ theta, float* __restrict__ tw, int n_theta)
{
    int i = blockIdx.x * blockDim.x + threadIdx.x;
    if (i < NE4) {
        float4 v = (i < NU4) ? U[i] : I[i - NU4];
        H[2 * i]     = __floats2half2_rn(v.x, v.y);
        H[2 * i + 1] = __floats2half2_rn(v.z, v.w);
    }
    if (i < NUM_NODES / 4)
        rs4[i] = make_float4(0.f, 0.f, 0.f, 0.f);
    if (i == 0) {
        float m = -1e30f;
        for (int k = 0; k < n_theta; k++) m = fmaxf(m, theta[k]);
        float s = 0.f; float w[8];
        for (int k = 0; k < n_theta; k++) { w[k] = expf(theta[k] - m); s += w[k]; }
        for (int k = 0; k < n_theta; k++) tw[k] = w[k] / s;
    }
}

// ---------------- path pass: exp(counts @ theta_w), row sums ---------------
// 2 edges per thread -> 3 aligned LDG.128 per thread, no smem, no barrier.
__global__ __launch_bounds__(256) void k_path1(
    const int* __restrict__ p_row, const float* __restrict__ p_counts,
    const float* __restrict__ tw, float* __restrict__ softv,
    float* __restrict__ rowsum, int n)
{
    const int t = blockIdx.x * blockDim.x + threadIdx.x;   // edge pair index
    const int e0 = 2 * t;
    if (e0 >= n) return;
    const float w0 = tw[0], w1 = tw[1], w2 = tw[2],
                w3 = tw[3], w4 = tw[4], w5 = tw[5];
    const float4* src = (const float4*)(p_counts + (size_t)e0 * 6);
    float4 a = src[0];
    float4 b = src[1];
    float4 c = src[2];
    float v0 = a.x * w0;
    v0 = fmaf(a.y, w1, v0); v0 = fmaf(a.z, w2, v0);
    v0 = fmaf(a.w, w3, v0); v0 = fmaf(b.x, w4, v0);
    v0 = fmaf(b.y, w5, v0);
    float ev0 = expf(v0);
    atomicAdd(&rowsum[p_row[e0]], ev0);
    if (e0 + 1 < n) {
        float v1 = b.z * w0;
        v1 = fmaf(b.w, w1, v1); v1 = fmaf(c.x, w2, v1);
        v1 = fmaf(c.y, w3, v1); v1 = fmaf(c.z, w4, v1);
        v1 = fmaf(c.w, w5, v1);
        float ev1 = expf(v1);
        *(float2*)(softv + e0) = make_float2(ev0, ev1);
        atomicAdd(&rowsum[p_row[e0 + 1]], ev1);
    } else {
        softv[e0] = ev0;
    }
}

// ---------------- vector reduction flush (2 instrs instead of 8) -----------
__device__ __forceinline__ void flushv4(float* __restrict__ y, int row, int ql,
                                        const float* acc)
{
    float* p = y + row * DIM + ql * 8;
    asm volatile("red.global.add.v4.f32 [%0], {%1,%2,%3,%4};"
                 :: "l"(p), "f"(acc[0]), "f"(acc[1]), "f"(acc[2]), "f"(acc[3])
                 : "memory");
    asm volatile("red.global.add.v4.f32 [%0], {%1,%2,%3,%4};"
                 :: "l"(p + 4), "f"(acc[4]), "f"(acc[5]), "f"(acc[6]), "f"(acc[7])
                 : "memory");
}

// ============================================================================
// Quarter-warp fp16 SpMM body with depth-1 gather prefetch (proven core).
// Warp = 4 quarters x 8 lanes; each quarter owns a contiguous edge sub-chunk;
// each lane owns 8 dims (one LDG.128 of fp16 per edge per lane).
// Rows sorted -> register accumulation, vector-red flush on row change.
// NORM: multiply edge value by 1/(rowsum[row]+eps) (path softmax fold).
// ============================================================================
template<bool NORM>
__device__ __forceinline__ void spmm_chunk(
    const int* __restrict__ rows, const int* __restrict__ cols,
    const float* __restrict__ vals, const float* __restrict__ rowsum,
    int base, int cnt, float scale,
    const uint4* __restrict__ x, float* __restrict__ y,
    float4* __restrict__ meta, int lane)
{
    for (int i = lane; i < cnt; i += 32) {
        int gi = base + i;
        meta[i] = make_float4(__int_as_float(rows[gi]), __int_as_float(cols[gi]),
                              vals[gi] * scale, 0.f);
    }
    __syncwarp();
    const int ql   = lane & 7;
    const int qbeg = (lane >> 3) * QE;
    const int qend = min(qbeg + QE, cnt);
    if (qbeg >= qend) return;

    float acc[8];
    #pragma unroll
    for (int k = 0; k < 8; k++) acc[k] = 0.f;
    int cur = -1; float inv = 1.f;

    // prime prefetch
    float4 md = meta[qbeg];
    uint4  hv = x[(size_t)__float_as_int(md.y) * 8 + ql];

    for (int j = qbeg; j < qend; j++) {
        // prefetch next edge's gather before consuming this one
        float4 mdn = md; uint4 hvn = hv;
        if (j + 1 < qend) {
            mdn = meta[j + 1];
            hvn = x[(size_t)__float_as_int(mdn.y) * 8 + ql];
        }
        int rj = __float_as_int(md.x);
        if (rj != cur) {
            if (cur >= 0) flushv4(y, cur, ql, acc);
            cur = rj;
            #pragma unroll
            for (int k = 0; k < 8; k++) acc[k] = 0.f;
            if (NORM) inv = 1.f / (rowsum[rj] + 1e-12f);
        }
        float f = NORM ? md.z * inv : md.z;
        float2 p0 = __half22float2(*(const __half2*)&hv.x);
        float2 p1 = __half22float2(*(const __half2*)&hv.y);
        float2 p2 = __half22float2(*(const __half2*)&hv.z);
        float2 p3 = __half22float2(*(const __half2*)&hv.w);
        acc[0] = fmaf(f, p0.x, acc[0]); acc[1] = fmaf(f, p0.y, acc[1]);
        acc[2] = fmaf(f, p1.x, acc[2]); acc[3] = fmaf(f, p1.y, acc[3]);
        acc[4] = fmaf(f, p2.x, acc[4]); acc[5] = fmaf(f, p2.y, acc[5]);
        acc[6] = fmaf(f, p3.x, acc[6]); acc[7] = fmaf(f, p3.y, acc[7]);
        md = mdn; hv = hvn;
    }
    flushv4(y, cur, ql, acc);
}

// ---------------- fused pos+neg layer SpMM ----------------------------------
__global__ __launch_bounds__(256) void k_spmm_dual(
    const int* __restrict__ prow, const int* __restrict__ pcol,
    const float* __restrict__ pval, int npos, int pos_blocks,
    const int* __restrict__ nrow, const int* __restrict__ ncol,
    const float* __restrict__ nval, int nneg,
    const uint4* __restrict__ x, float* __restrict__ y)
{
    __shared__ float4 meta[8][WEDGES];
    const int wslot = threadIdx.x >> 5;
    const int lane  = threadIdx.x & 31;

    const bool isneg = (blockIdx.x >= pos_blocks);
    const int  bid   = isneg ? (blockIdx.x - pos_blocks) : blockIdx.x;
    const int* rows  = isneg ? nrow : prow;
    const int* cols  = isneg ? ncol : pcol;
    const float* vals = isneg ? nval : pval;
    const int  n     = isneg ? nneg : npos;
    const float scale = isneg ? -ALPHA : 1.0f;

    const int base = (bid * 8 + wslot) * WEDGES;
    if (base >= n) return;
    const int cnt = min(WEDGES, n - base);
    spmm_chunk<false>(rows, cols, vals, nullptr, base, cnt, scale, x, y,
                      meta[wslot], lane);
}

// ---------------- path SpMM (fp16 gather + fused softmax normalization) ----
__global__ __launch_bounds__(256) void k_spmm_path(
    const int* __restrict__ rows, const int* __restrict__ cols,
    const float* __restrict__ evals, const float* __restrict__ rowsum, int n,
    const uint4* __restrict__ x, float* __restrict__ y)
{
    __shared__ float4 meta[8][WEDGES];
    const int wslot = threadIdx.x >> 5;
    const int lane  = threadIdx.x & 31;
    const int base  = (blockIdx.x * 8 + wslot) * WEDGES;
    if (base >= n) return;
    const int cnt = min(WEDGES, n - base);
    spmm_chunk<true>(rows, cols, evals, rowsum, base, cnt, 1.0f, x, y,
                     meta[wslot], lane);
}

// ---------------- e0 epilogue: H0 = half(t); t = 0  (2 float4 / thread) -----
__global__ void k_init(float4* __restrict__ T, __half2* __restrict__ H, int n4)
{
    int i = (blockIdx.x * blockDim.x + threadIdx.x) * 2;
    if (i >= n4) return;
    float4 t0 = __ldcs(&T[i]);
    float4 t1 = __ldcs(&T[i + 1]);
    H[2 * i]     = __floats2half2_rn(t0.x, t0.y);
    H[2 * i + 1] = __floats2half2_rn(t0.z, t0.w);
    H[2 * i + 2] = __floats2half2_rn(t1.x, t1.y);
    H[2 * i + 3] = __floats2half2_rn(t1.z, t1.w);
    const float4 z = make_float4(0.f, 0.f, 0.f, 0.f);
    __stcs(&T[i], z);
    __stcs(&T[i + 1], z);
}

// ---------------- layer epilogue: Hnew = half(t + a*Hold); t = 0 ------------
__global__ void k_layer(float4* __restrict__ T, const __half2* __restrict__ Hold,
                        __half2* __restrict__ Hnew, int n4)
{
    int i = (blockIdx.x * blockDim.x + threadIdx.x) * 2;
    if (i >= n4) return;
    float4 t0 = __ldcs(&T[i]);
    float4 t1 = __ldcs(&T[i + 1]);
    float2 e0 = __half22float2(Hold[2 * i]);
    float2 e1 = __half22float2(Hold[2 * i + 1]);
    float2 e2 = __half22float2(Hold[2 * i + 2]);
    float2 e3 = __half22float2(Hold[2 * i + 3]);
    Hnew[2 * i]     = __floats2half2_rn(fmaf(ALPHA, e0.x, t0.x), fmaf(ALPHA, e0.y, t0.y));
    Hnew[2 * i + 1] = __floats2half2_rn(fmaf(ALPHA, e1.x, t0.z), fmaf(ALPHA, e1.y, t0.w));
    Hnew[2 * i + 2] = __floats2half2_rn(fmaf(ALPHA, e2.x, t1.x), fmaf(ALPHA, e2.y, t1.y));
    Hnew[2 * i + 3] = __floats2half2_rn(fmaf(ALPHA, e3.x, t1.z), fmaf(ALPHA, e3.y, t1.w));
    const float4 z = make_float4(0.f, 0.f, 0.f, 0.f);
    __stcs(&T[i], z);
    __stcs(&T[i + 1], z);
}

// ---------------- final: out = (H0 + H1 + H2 + (t + a*H2))/4; t = 0 ---------
__global__ void k_final(float4* __restrict__ T,
                        const __half2* __restrict__ H0,
                        const __half2* __restrict__ H1,
                        const __half2* __restrict__ H2,
                        float4* __restrict__ O, int n4)
{
    int i = (blockIdx.x * blockDim.x + threadIdx.x) * 2;
    if (i >= n4) return;
    #pragma unroll
    for (int u = 0; u < 2; u++) {
        float4 t = __ldcs(&T[i + u]);
        float2 a01 = __half22float2(H0[2 * (i + u)]);
        float2 a23 = __half22float2(H0[2 * (i + u) + 1]);
        float2 b01 = __half22float2(H1[2 * (i + u)]);
        float2 b23 = __half22float2(H1[2 * (i + u) + 1]);
        float2 c01 = __half22float2(H2[2 * (i + u)]);
        float2 c23 = __half22float2(H2[2 * (i + u) + 1]);
        float4 o;
        o.x = (a01.x + b01.x + c01.x + fmaf(ALPHA, c01.x, t.x)) * 0.25f;
        o.y = (a01.y + b01.y + c01.y + fmaf(ALPHA, c01.y, t.y)) * 0.25f;
        o.z = (a23.x + b23.x + c23.x + fmaf(ALPHA, c23.x, t.z)) * 0.25f;
        o.w = (a23.y + b23.y + c23.y + fmaf(ALPHA, c23.y, t.w)) * 0.25f;
        __stcs(&O[i + u], o);
        __stcs(&T[i + u], make_float4(0.f, 0.f, 0.f, 0.f));   // keep invariant
    }
}

// ---------------------------------------------------------------------------
extern "C" void kernel_launch(void* const* d_in, const int* in_sizes, int n_in,
                              void* d_out, int out_size)
{
    const float* user_emb = (const float*)d_in[0];
    const float* item_emb = (const float*)d_in[1];
    const float* theta    = (const float*)d_in[2];
    const int*   pos_row  = (const int*)d_in[3];
    const int*   pos_col  = (const int*)d_in[4];
    const float* pos_val  = (const float*)d_in[5];
    const int*   neg_row  = (const int*)d_in[6];
    const int*   neg_col  = (const int*)d_in[7];
    const float* neg_val  = (const float*)d_in[8];
    const int*   p_row    = (const int*)d_in[9];
    const int*   p_col    = (const int*)d_in[10];
    const float* p_counts = (const float*)d_in[11];

    const int n_pos  = in_sizes[3];
    const int n_neg  = in_sizes[6];
    int n_path = in_sizes[9];
    if (n_path > MAX_EPATH) n_path = MAX_EPATH;
    const int n_theta = in_sizes[2] < 8 ? in_sizes[2] : 8;

    float *pt, *psv, *prs, *ptw;
    __half2 *hin, *h0, *h1, *h2;
    cudaGetSymbolAddress((void**)&pt,  g_t);
    cudaGetSymbolAddress((void**)&hin, g_hin);
    cudaGetSymbolAddress((void**)&h0,  g_h0);
    cudaGetSymbolAddress((void**)&h1,  g_h1);
    cudaGetSymbolAddress((void**)&h2,  g_h2);
    cudaGetSymbolAddress((void**)&psv, g_softv);
    cudaGetSymbolAddress((void**)&prs, g_rowsum);
    cudaGetSymbolAddress((void**)&ptw, g_thetaw);

    const int TB = 256;
    const int ew_grid = (NE4 / 2 + TB - 1) / TB;   // elementwise: 2 float4/thread

    // fused prologue: fp16 input table + rowsum zero + theta softmax
    k_prologue<<<(NE4 + TB - 1) / TB, TB>>>((const float4*)user_emb,
                                            (const float4*)item_emb, hin,
                                            (float4*)prs, theta, ptw, n_theta);

    // path edge weights (exp + rowsums); normalization folded into spmm
    {
        int pairs = (n_path + 1) / 2;
        k_path1<<<(pairs + TB - 1) / TB, TB>>>(p_row, p_counts, ptw, psv, prs, n_path);
    }

    // e0 = spmm(path, softv/rowsum, hin) -> t
    {
        int warps = (n_path + WEDGES - 1) / WEDGES;
        k_spmm_path<<<(warps + 7) / 8, TB>>>(p_row, p_col, psv, prs, n_path,
                                             (const uint4*)hin, pt);
    }

    // H0 = half(e0); t = 0
    k_init<<<ew_grid, TB>>>((float4*)pt, h0, NE4);

    const int pos_blocks = ((n_pos + WEDGES - 1) / WEDGES + 7) / 8;
    const int neg_blocks = ((n_neg + WEDGES - 1) / WEDGES + 7) / 8;
    const int dual_grid  = pos_blocks + neg_blocks;

    // layer 1
    k_spmm_dual<<<dual_grid, TB>>>(pos_row, pos_col, pos_val, n_pos, pos_blocks,
                                   neg_row, neg_col, neg_val, n_neg,
                                   (const uint4*)h0, pt);
    k_layer<<<ew_grid, TB>>>((float4*)pt, h0, h1, NE4);

    // layer 2
    k_spmm_dual<<<dual_grid, TB>>>(pos_row, pos_col, pos_val, n_pos, pos_blocks,
                                   neg_row, neg_col, neg_val, n_neg,
                                   (const uint4*)h1, pt);
    k_layer<<<ew_grid, TB>>>((float4*)pt, h1, h2, NE4);

    // layer 3 + fused final mean
    k_spmm_dual<<<dual_grid, TB>>>(pos_row, pos_col, pos_val, n_pos, pos_blocks,
                                   neg_row, neg_col, neg_val, n_neg,
                                   (const uint4*)h2, pt);
    k_final<<<ew_grid, TB>>>((float4*)pt, h0, h1, h2, (float4*)d_out, NE4);
}

// round 10
// speedup vs baseline: 1.2377x; 1.0385x over previous
#include <cuda_runtime.h>
#include <cuda_fp16.h>

#define NUM_USERS 80000
#define NUM_ITEMS 40000
#define NUM_NODES 120000
#define DIM       64
#define NE        (NUM_NODES * DIM)     // 7,680,000
#define NE4       (NE / 4)              // 1,920,000
#define NU4       (NUM_USERS * DIM / 4) // 1,280,000
#define ALPHA     0.8f
#define MAX_EPATH 2000000
#define WEDGES    128                    // edges per warp (proven config)
#define QE        (WEDGES / 4)           // edges per quarter-warp (32)

// ---------------- scratch (device globals; zero-initialized .bss) ----------
__device__ __align__(256) float   g_t[NE];        // fp32 scatter target (zero at entry, restored at exit)
__device__ __align__(256) __half2 g_hin[NE / 2];  // fp16 copy of [user_emb; item_emb]
__device__ __align__(256) __half2 g_h0[NE / 2];   // e0 (fp16)
__device__ __align__(256) __half2 g_h1[NE / 2];   // e1 (fp16)
__device__ __align__(256) __half2 g_h2[NE / 2];   // e2 (fp16)
__device__ __align__(256) float   g_softv[MAX_EPATH];
__device__ __align__(256) float   g_rowsum[NUM_NODES];
__device__ __align__(256) float   g_thetaw[8];

// ---------------- fused prologue: cvt + rowsum zero + theta softmax --------
__global__ __launch_bounds__(256) void k_prologue(
    const float4* __restrict__ U, const float4* __restrict__ I,
    __half2* __restrict__ H, float4* __restrict__ rs4,
    const float* __restrict__ theta, float* __restrict__ tw, int n_theta)
{
    int i = blockIdx.x * blockDim.x + threadIdx.x;
    if (i < NE4) {
        float4 v = (i < NU4) ? U[i] : I[i - NU4];
        H[2 * i]     = __floats2half2_rn(v.x, v.y);
        H[2 * i + 1] = __floats2half2_rn(v.z, v.w);
    }
    if (i < NUM_NODES / 4)
        rs4[i] = make_float4(0.f, 0.f, 0.f, 0.f);
    if (i == 0) {
        float m = -1e30f;
        for (int k = 0; k < n_theta; k++) m = fmaxf(m, theta[k]);
        float s = 0.f; float w[8];
        for (int k = 0; k < n_theta; k++) { w[k] = expf(theta[k] - m); s += w[k]; }
        for (int k = 0; k < n_theta; k++) tw[k] = w[k] / s;
    }
}

// ---------------- path pass: exp(counts @ theta_w), row sums ---------------
// 2 edges per thread -> 3 aligned LDG.128 per thread, no smem, no barrier.
__global__ __launch_bounds__(256) void k_path1(
    const int* __restrict__ p_row, const float* __restrict__ p_counts,
    const float* __restrict__ tw, float* __restrict__ softv,
    float* __restrict__ rowsum, int n)
{
    const int t = blockIdx.x * blockDim.x + threadIdx.x;   // edge pair index
    const int e0 = 2 * t;
    if (e0 >= n) return;
    const float w0 = tw[0], w1 = tw[1], w2 = tw[2],
                w3 = tw[3], w4 = tw[4], w5 = tw[5];
    const float4* src = (const float4*)(p_counts + (size_t)e0 * 6);
    float4 a = src[0];
    float4 b = src[1];
    float4 c = src[2];
    float v0 = a.x * w0;
    v0 = fmaf(a.y, w1, v0); v0 = fmaf(a.z, w2, v0);
    v0 = fmaf(a.w, w3, v0); v0 = fmaf(b.x, w4, v0);
    v0 = fmaf(b.y, w5, v0);
    float ev0 = expf(v0);
    atomicAdd(&rowsum[p_row[e0]], ev0);
    if (e0 + 1 < n) {
        float v1 = b.z * w0;
        v1 = fmaf(b.w, w1, v1); v1 = fmaf(c.x, w2, v1);
        v1 = fmaf(c.y, w3, v1); v1 = fmaf(c.z, w4, v1);
        v1 = fmaf(c.w, w5, v1);
        float ev1 = expf(v1);
        *(float2*)(softv + e0) = make_float2(ev0, ev1);
        atomicAdd(&rowsum[p_row[e0 + 1]], ev1);
    } else {
        softv[e0] = ev0;
    }
}

// ---------------- vector reduction flush (2 instrs instead of 8) -----------
__device__ __forceinline__ void flushv4(float* __restrict__ y, int row, int ql,
                                        const float* acc)
{
    float* p = y + row * DIM + ql * 8;
    asm volatile("red.global.add.v4.f32 [%0], {%1,%2,%3,%4};"
                 :: "l"(p), "f"(acc[0]), "f"(acc[1]), "f"(acc[2]), "f"(acc[3])
                 : "memory");
    asm volatile("red.global.add.v4.f32 [%0], {%1,%2,%3,%4};"
                 :: "l"(p + 4), "f"(acc[4]), "f"(acc[5]), "f"(acc[6]), "f"(acc[7])
                 : "memory");
}

// ============================================================================
// Quarter-warp fp16 SpMM body with depth-1 gather prefetch (proven core).
// Warp = 4 quarters x 8 lanes; each quarter owns a contiguous edge sub-chunk;
// each lane owns 8 dims (one LDG.128 of fp16 per edge per lane).
// Rows sorted -> register accumulation, vector-red flush on row change.
// NORM: edge value is divided by (rowsum[row]+eps) in the PARALLEL staging
// phase (latency hidden), keeping the serial inner loop free of dependent
// rowsum loads / divides.
// ============================================================================
template<bool NORM>
__device__ __forceinline__ void spmm_chunk(
    const int* __restrict__ rows, const int* __restrict__ cols,
    const float* __restrict__ vals, const float* __restrict__ rowsum,
    int base, int cnt, float scale,
    const uint4* __restrict__ x, float* __restrict__ y,
    float4* __restrict__ meta, int lane)
{
    for (int i = lane; i < cnt; i += 32) {
        int gi = base + i;
        int r  = rows[gi];
        float v = vals[gi];
        if (NORM) v = v / (rowsum[r] + 1e-12f);
        else      v = v * scale;
        meta[i] = make_float4(__int_as_float(r), __int_as_float(cols[gi]), v, 0.f);
    }
    __syncwarp();
    const int ql   = lane & 7;
    const int qbeg = (lane >> 3) * QE;
    const int qend = min(qbeg + QE, cnt);
    if (qbeg >= qend) return;

    float acc[8];
    #pragma unroll
    for (int k = 0; k < 8; k++) acc[k] = 0.f;
    int cur = -1;

    // prime prefetch
    float4 md = meta[qbeg];
    uint4  hv = x[(size_t)__float_as_int(md.y) * 8 + ql];

    for (int j = qbeg; j < qend; j++) {
        // prefetch next edge's gather before consuming this one
        float4 mdn = md; uint4 hvn = hv;
        if (j + 1 < qend) {
            mdn = meta[j + 1];
            hvn = x[(size_t)__float_as_int(mdn.y) * 8 + ql];
        }
        int rj = __float_as_int(md.x);
        if (rj != cur) {
            if (cur >= 0) flushv4(y, cur, ql, acc);
            cur = rj;
            #pragma unroll
            for (int k = 0; k < 8; k++) acc[k] = 0.f;
        }
        float f = md.z;
        float2 p0 = __half22float2(*(const __half2*)&hv.x);
        float2 p1 = __half22float2(*(const __half2*)&hv.y);
        float2 p2 = __half22float2(*(const __half2*)&hv.z);
        float2 p3 = __half22float2(*(const __half2*)&hv.w);
        acc[0] = fmaf(f, p0.x, acc[0]); acc[1] = fmaf(f, p0.y, acc[1]);
        acc[2] = fmaf(f, p1.x, acc[2]); acc[3] = fmaf(f, p1.y, acc[3]);
        acc[4] = fmaf(f, p2.x, acc[4]); acc[5] = fmaf(f, p2.y, acc[5]);
        acc[6] = fmaf(f, p3.x, acc[6]); acc[7] = fmaf(f, p3.y, acc[7]);
        md = mdn; hv = hvn;
    }
    flushv4(y, cur, ql, acc);
}

// ---------------- fused pos+neg layer SpMM ----------------------------------
__global__ __launch_bounds__(256) void k_spmm_dual(
    const int* __restrict__ prow, const int* __restrict__ pcol,
    const float* __restrict__ pval, int npos, int pos_blocks,
    const int* __restrict__ nrow, const int* __restrict__ ncol,
    const float* __restrict__ nval, int nneg,
    const uint4* __restrict__ x, float* __restrict__ y)
{
    __shared__ float4 meta[8][WEDGES];
    const int wslot = threadIdx.x >> 5;
    const int lane  = threadIdx.x & 31;

    const bool isneg = (blockIdx.x >= pos_blocks);
    const int  bid   = isneg ? (blockIdx.x - pos_blocks) : blockIdx.x;
    const int* rows  = isneg ? nrow : prow;
    const int* cols  = isneg ? ncol : pcol;
    const float* vals = isneg ? nval : pval;
    const int  n     = isneg ? nneg : npos;
    const float scale = isneg ? -ALPHA : 1.0f;

    const int base = (bid * 8 + wslot) * WEDGES;
    if (base >= n) return;
    const int cnt = min(WEDGES, n - base);
    spmm_chunk<false>(rows, cols, vals, nullptr, base, cnt, scale, x, y,
                      meta[wslot], lane);
}

// ---------------- path SpMM (fp16 gather + staged softmax normalization) ---
__global__ __launch_bounds__(256) void k_spmm_path(
    const int* __restrict__ rows, const int* __restrict__ cols,
    const float* __restrict__ evals, const float* __restrict__ rowsum, int n,
    const uint4* __restrict__ x, float* __restrict__ y)
{
    __shared__ float4 meta[8][WEDGES];
    const int wslot = threadIdx.x >> 5;
    const int lane  = threadIdx.x & 31;
    const int base  = (blockIdx.x * 8 + wslot) * WEDGES;
    if (base >= n) return;
    const int cnt = min(WEDGES, n - base);
    spmm_chunk<true>(rows, cols, evals, rowsum, base, cnt, 1.0f, x, y,
                     meta[wslot], lane);
}

// ---------------- e0 epilogue: H0 = half(t); t = 0 ---------------------------
__global__ void k_init(float4* __restrict__ T, __half2* __restrict__ H, int n4)
{
    int i = blockIdx.x * blockDim.x + threadIdx.x;
    if (i >= n4) return;
    float4 t = T[i];
    H[2 * i]     = __floats2half2_rn(t.x, t.y);
    H[2 * i + 1] = __floats2half2_rn(t.z, t.w);
    T[i] = make_float4(0.f, 0.f, 0.f, 0.f);
}

// ---------------- layer epilogue: Hnew = half(t + a*Hold); t = 0 -------------
__global__ void k_layer(float4* __restrict__ T, const __half2* __restrict__ Hold,
                        __half2* __restrict__ Hnew, int n4)
{
    int i = blockIdx.x * blockDim.x + threadIdx.x;
    if (i >= n4) return;
    float4 t = T[i];
    float2 e01 = __half22float2(Hold[2 * i]);
    float2 e23 = __half22float2(Hold[2 * i + 1]);
    Hnew[2 * i]     = __floats2half2_rn(fmaf(ALPHA, e01.x, t.x), fmaf(ALPHA, e01.y, t.y));
    Hnew[2 * i + 1] = __floats2half2_rn(fmaf(ALPHA, e23.x, t.z), fmaf(ALPHA, e23.y, t.w));
    T[i] = make_float4(0.f, 0.f, 0.f, 0.f);
}

// ---------------- final: out = (H0 + H1 + H2 + (t + a*H2))/4; t = 0 ----------
__global__ void k_final(float4* __restrict__ T,
                        const __half2* __restrict__ H0,
                        const __half2* __restrict__ H1,
                        const __half2* __restrict__ H2,
                        float4* __restrict__ O, int n4)
{
    int i = blockIdx.x * blockDim.x + threadIdx.x;
    if (i >= n4) return;
    float4 t = T[i];
    float2 a01 = __half22float2(H0[2 * i]);
    float2 a23 = __half22float2(H0[2 * i + 1]);
    float2 b01 = __half22float2(H1[2 * i]);
    float2 b23 = __half22float2(H1[2 * i + 1]);
    float2 c01 = __half22float2(H2[2 * i]);
    float2 c23 = __half22float2(H2[2 * i + 1]);
    float4 o;
    o.x = (a01.x + b01.x + c01.x + fmaf(ALPHA, c01.x, t.x)) * 0.25f;
    o.y = (a01.y + b01.y + c01.y + fmaf(ALPHA, c01.y, t.y)) * 0.25f;
    o.z = (a23.x + b23.x + c23.x + fmaf(ALPHA, c23.x, t.z)) * 0.25f;
    o.w = (a23.y + b23.y + c23.y + fmaf(ALPHA, c23.y, t.w)) * 0.25f;
    O[i] = o;
    T[i] = make_float4(0.f, 0.f, 0.f, 0.f);   // keep zero-at-entry invariant
}

// ---------------------------------------------------------------------------
extern "C" void kernel_launch(void* const* d_in, const int* in_sizes, int n_in,
                              void* d_out, int out_size)
{
    const float* user_emb = (const float*)d_in[0];
    const float* item_emb = (const float*)d_in[1];
    const float* theta    = (const float*)d_in[2];
    const int*   pos_row  = (const int*)d_in[3];
    const int*   pos_col  = (const int*)d_in[4];
    const float* pos_val  = (const float*)d_in[5];
    const int*   neg_row  = (const int*)d_in[6];
    const int*   neg_col  = (const int*)d_in[7];
    const float* neg_val  = (const float*)d_in[8];
    const int*   p_row    = (const int*)d_in[9];
    const int*   p_col    = (const int*)d_in[10];
    const float* p_counts = (const float*)d_in[11];

    const int n_pos  = in_sizes[3];
    const int n_neg  = in_sizes[6];
    int n_path = in_sizes[9];
    if (n_path > MAX_EPATH) n_path = MAX_EPATH;
    const int n_theta = in_sizes[2] < 8 ? in_sizes[2] : 8;

    float *pt, *psv, *prs, *ptw;
    __half2 *hin, *h0, *h1, *h2;
    cudaGetSymbolAddress((void**)&pt,  g_t);
    cudaGetSymbolAddress((void**)&hin, g_hin);
    cudaGetSymbolAddress((void**)&h0,  g_h0);
    cudaGetSymbolAddress((void**)&h1,  g_h1);
    cudaGetSymbolAddress((void**)&h2,  g_h2);
    cudaGetSymbolAddress((void**)&psv, g_softv);
    cudaGetSymbolAddress((void**)&prs, g_rowsum);
    cudaGetSymbolAddress((void**)&ptw, g_thetaw);

    const int TB = 256;

    // fused prologue: fp16 input table + rowsum zero + theta softmax
    k_prologue<<<(NE4 + TB - 1) / TB, TB>>>((const float4*)user_emb,
                                            (const float4*)item_emb, hin,
                                            (float4*)prs, theta, ptw, n_theta);

    // path edge weights (exp + rowsums); normalization staged into spmm
    {
        int pairs = (n_path + 1) / 2;
        k_path1<<<(pairs + TB - 1) / TB, TB>>>(p_row, p_counts, ptw, psv, prs, n_path);
    }

    // e0 = spmm(path, softv/rowsum, hin) -> t
    {
        int warps = (n_path + WEDGES - 1) / WEDGES;
        k_spmm_path<<<(warps + 7) / 8, TB>>>(p_row, p_col, psv, prs, n_path,
                                             (const uint4*)hin, pt);
    }

    // H0 = half(e0); t = 0
    k_init<<<(NE4 + TB - 1) / TB, TB>>>((float4*)pt, h0, NE4);

    const int pos_blocks = ((n_pos + WEDGES - 1) / WEDGES + 7) / 8;
    const int neg_blocks = ((n_neg + WEDGES - 1) / WEDGES + 7) / 8;
    const int dual_grid  = pos_blocks + neg_blocks;

    // layer 1
    k_spmm_dual<<<dual_grid, TB>>>(pos_row, pos_col, pos_val, n_pos, pos_blocks,
                                   neg_row, neg_col, neg_val, n_neg,
                                   (const uint4*)h0, pt);
    k_layer<<<(NE4 + TB - 1) / TB, TB>>>((float4*)pt, h0, h1, NE4);

    // layer 2
    k_spmm_dual<<<dual_grid, TB>>>(pos_row, pos_col, pos_val, n_pos, pos_blocks,
                                   neg_row, neg_col, neg_val, n_neg,
                                   (const uint4*)h1, pt);
    k_layer<<<(NE4 + TB - 1) / TB, TB>>>((float4*)pt, h1, h2, NE4);

    // layer 3 + fused final mean
    k_spmm_dual<<<dual_grid, TB>>>(pos_row, pos_col, pos_val, n_pos, pos_blocks,
                                   neg_row, neg_col, neg_val, n_neg,
                                   (const uint4*)h2, pt);
    k_final<<<(NE4 + TB - 1) / TB, TB>>>((float4*)pt, h0, h1, h2,
                                         (float4*)d_out, NE4);
}

// round 11
// speedup vs baseline: 1.2658x; 1.0227x over previous
#include <cuda_runtime.h>
#include <cuda_fp16.h>

#define NUM_USERS 80000
#define NUM_ITEMS 40000
#define NUM_NODES 120000
#define DIM       64
#define NE        (NUM_NODES * DIM)     // 7,680,000
#define NE4       (NE / 4)              // 1,920,000
#define NU4       (NUM_USERS * DIM / 4) // 1,280,000
#define ALPHA     0.8f
#define MAX_EPATH 2000000
#define WEDGES    128                    // edges per warp (proven config)
#define QE        (WEDGES / 4)           // edges per quarter-warp (32)

// ---------------- scratch (device globals; zero-initialized .bss) ----------
__device__ __align__(256) float   g_t[NE];        // fp32 accumulator (zero at entry, restored at exit)
__device__ __align__(256) __half2 g_hin[NE / 2];  // fp16 copy of [user_emb; item_emb]
__device__ __align__(256) __half2 g_h0[NE / 2];   // e0 (fp16)
__device__ __align__(256) __half2 g_h1[NE / 2];   // e1 (fp16)
__device__ __align__(256) __half2 g_h2[NE / 2];   // e2 (fp16)
__device__ __align__(256) float   g_softv[MAX_EPATH];
__device__ __align__(256) float   g_rowsum[NUM_NODES];
__device__ __align__(256) float   g_thetaw[8];

// ---------------- fused prologue: cvt + rowsum zero + theta softmax --------
__global__ __launch_bounds__(256) void k_prologue(
    const float4* __restrict__ U, const float4* __restrict__ I,
    __half2* __restrict__ H, float4* __restrict__ rs4,
    const float* __restrict__ theta, float* __restrict__ tw, int n_theta)
{
    int i = blockIdx.x * blockDim.x + threadIdx.x;
    if (i < NE4) {
        float4 v = (i < NU4) ? U[i] : I[i - NU4];
        H[2 * i]     = __floats2half2_rn(v.x, v.y);
        H[2 * i + 1] = __floats2half2_rn(v.z, v.w);
    }
    if (i < NUM_NODES / 4)
        rs4[i] = make_float4(0.f, 0.f, 0.f, 0.f);
    if (i == 0) {
        float m = -1e30f;
        for (int k = 0; k < n_theta; k++) m = fmaxf(m, theta[k]);
        float s = 0.f; float w[8];
        for (int k = 0; k < n_theta; k++) { w[k] = expf(theta[k] - m); s += w[k]; }
        for (int k = 0; k < n_theta; k++) tw[k] = w[k] / s;
    }
}

// ---------------- path pass: exp(counts @ theta_w), row sums ---------------
// 2 edges per thread -> 3 aligned LDG.128 per thread, no smem, no barrier.
__global__ __launch_bounds__(256) void k_path1(
    const int* __restrict__ p_row, const float* __restrict__ p_counts,
    const float* __restrict__ tw, float* __restrict__ softv,
    float* __restrict__ rowsum, int n)
{
    const int t = blockIdx.x * blockDim.x + threadIdx.x;   // edge pair index
    const int e0 = 2 * t;
    if (e0 >= n) return;
    const float w0 = tw[0], w1 = tw[1], w2 = tw[2],
                w3 = tw[3], w4 = tw[4], w5 = tw[5];
    const float4* src = (const float4*)(p_counts + (size_t)e0 * 6);
    float4 a = src[0];
    float4 b = src[1];
    float4 c = src[2];
    float v0 = a.x * w0;
    v0 = fmaf(a.y, w1, v0); v0 = fmaf(a.z, w2, v0);
    v0 = fmaf(a.w, w3, v0); v0 = fmaf(b.x, w4, v0);
    v0 = fmaf(b.y, w5, v0);
    float ev0 = expf(v0);
    atomicAdd(&rowsum[p_row[e0]], ev0);
    if (e0 + 1 < n) {
        float v1 = b.z * w0;
        v1 = fmaf(b.w, w1, v1); v1 = fmaf(c.x, w2, v1);
        v1 = fmaf(c.y, w3, v1); v1 = fmaf(c.z, w4, v1);
        v1 = fmaf(c.w, w5, v1);
        float ev1 = expf(v1);
        *(float2*)(softv + e0) = make_float2(ev0, ev1);
        atomicAdd(&rowsum[p_row[e0 + 1]], ev1);
    } else {
        softv[e0] = ev0;
    }
}

// ---------------- vector reduction flush (2 instrs instead of 8) -----------
__device__ __forceinline__ void flushv4(float* __restrict__ y, int row, int ql,
                                        const float* acc)
{
    float* p = y + row * DIM + ql * 8;
    asm volatile("red.global.add.v4.f32 [%0], {%1,%2,%3,%4};"
                 :: "l"(p), "f"(acc[0]), "f"(acc[1]), "f"(acc[2]), "f"(acc[3])
                 : "memory");
    asm volatile("red.global.add.v4.f32 [%0], {%1,%2,%3,%4};"
                 :: "l"(p + 4), "f"(acc[4]), "f"(acc[5]), "f"(acc[6]), "f"(acc[7])
                 : "memory");
}

// ============================================================================
// Quarter-warp fp16 SpMM body with depth-1 gather prefetch (proven R6 core,
// NORM machinery removed entirely — softmax normalization now happens
// per-row in k_init since rowsum is constant within a row).
// ============================================================================
__device__ __forceinline__ void spmm_chunk(
    const int* __restrict__ rows, const int* __restrict__ cols,
    const float* __restrict__ vals,
    int base, int cnt, float scale,
    const uint4* __restrict__ x, float* __restrict__ y,
    float4* __restrict__ meta, int lane)
{
    for (int i = lane; i < cnt; i += 32) {
        int gi = base + i;
        meta[i] = make_float4(__int_as_float(rows[gi]), __int_as_float(cols[gi]),
                              vals[gi] * scale, 0.f);
    }
    __syncwarp();
    const int ql   = lane & 7;
    const int qbeg = (lane >> 3) * QE;
    const int qend = min(qbeg + QE, cnt);
    if (qbeg >= qend) return;

    float acc[8];
    #pragma unroll
    for (int k = 0; k < 8; k++) acc[k] = 0.f;
    int cur = -1;

    // prime prefetch
    float4 md = meta[qbeg];
    uint4  hv = x[(size_t)__float_as_int(md.y) * 8 + ql];

    for (int j = qbeg; j < qend; j++) {
        // prefetch next edge's gather before consuming this one
        float4 mdn = md; uint4 hvn = hv;
        if (j + 1 < qend) {
            mdn = meta[j + 1];
            hvn = x[(size_t)__float_as_int(mdn.y) * 8 + ql];
        }
        int rj = __float_as_int(md.x);
        if (rj != cur) {
            if (cur >= 0) flushv4(y, cur, ql, acc);
            cur = rj;
            #pragma unroll
            for (int k = 0; k < 8; k++) acc[k] = 0.f;
        }
        float f = md.z;
        float2 p0 = __half22float2(*(const __half2*)&hv.x);
        float2 p1 = __half22float2(*(const __half2*)&hv.y);
        float2 p2 = __half22float2(*(const __half2*)&hv.z);
        float2 p3 = __half22float2(*(const __half2*)&hv.w);
        acc[0] = fmaf(f, p0.x, acc[0]); acc[1] = fmaf(f, p0.y, acc[1]);
        acc[2] = fmaf(f, p1.x, acc[2]); acc[3] = fmaf(f, p1.y, acc[3]);
        acc[4] = fmaf(f, p2.x, acc[4]); acc[5] = fmaf(f, p2.y, acc[5]);
        acc[6] = fmaf(f, p3.x, acc[6]); acc[7] = fmaf(f, p3.y, acc[7]);
        md = mdn; hv = hvn;
    }
    flushv4(y, cur, ql, acc);
}

// ---------------- fused pos+neg layer SpMM ----------------------------------
__global__ __launch_bounds__(256) void k_spmm_dual(
    const int* __restrict__ prow, const int* __restrict__ pcol,
    const float* __restrict__ pval, int npos, int pos_blocks,
    const int* __restrict__ nrow, const int* __restrict__ ncol,
    const float* __restrict__ nval, int nneg,
    const uint4* __restrict__ x, float* __restrict__ y)
{
    __shared__ float4 meta[8][WEDGES];
    const int wslot = threadIdx.x >> 5;
    const int lane  = threadIdx.x & 31;

    const bool isneg = (blockIdx.x >= pos_blocks);
    const int  bid   = isneg ? (blockIdx.x - pos_blocks) : blockIdx.x;
    const int* rows  = isneg ? nrow : prow;
    const int* cols  = isneg ? ncol : pcol;
    const float* vals = isneg ? nval : pval;
    const int  n     = isneg ? nneg : npos;
    const float scale = isneg ? -ALPHA : 1.0f;

    const int base = (bid * 8 + wslot) * WEDGES;
    if (base >= n) return;
    const int cnt = min(WEDGES, n - base);
    spmm_chunk(rows, cols, vals, base, cnt, scale, x, y, meta[wslot], lane);
}

// ---------------- path SpMM (unnormalized; same body as dual) ---------------
__global__ __launch_bounds__(256) void k_spmm_path(
    const int* __restrict__ rows, const int* __restrict__ cols,
    const float* __restrict__ evals, int n,
    const uint4* __restrict__ x, float* __restrict__ y)
{
    __shared__ float4 meta[8][WEDGES];
    const int wslot = threadIdx.x >> 5;
    const int lane  = threadIdx.x & 31;
    const int base  = (blockIdx.x * 8 + wslot) * WEDGES;
    if (base >= n) return;
    const int cnt = min(WEDGES, n - base);
    spmm_chunk(rows, cols, evals, base, cnt, 1.0f, x, y, meta[wslot], lane);
}

// ---------------- e0 epilogue: e0 = t/rowsum; H0 = half(e0); t = a*e0 -------
__global__ void k_init(float4* __restrict__ T, __half2* __restrict__ H,
                       const float* __restrict__ rowsum, int n4)
{
    int i = blockIdx.x * blockDim.x + threadIdx.x;
    if (i >= n4) return;
    const float inv = 1.f / (rowsum[i >> 4] + 1e-12f);   // 16 float4s per node row
    float4 t = T[i];
    t.x *= inv; t.y *= inv; t.z *= inv; t.w *= inv;
    H[2 * i]     = __floats2half2_rn(t.x, t.y);
    H[2 * i + 1] = __floats2half2_rn(t.z, t.w);
    T[i] = make_float4(ALPHA * t.x, ALPHA * t.y, ALPHA * t.z, ALPHA * t.w);
}

// ---------------- layer epilogue: e_new = t; Hnew = half(t); t = a*t --------
__global__ void k_layer(float4* __restrict__ T, __half2* __restrict__ Hnew, int n4)
{
    int i = blockIdx.x * blockDim.x + threadIdx.x;
    if (i >= n4) return;
    float4 t = T[i];
    Hnew[2 * i]     = __floats2half2_rn(t.x, t.y);
    Hnew[2 * i + 1] = __floats2half2_rn(t.z, t.w);
    T[i] = make_float4(ALPHA * t.x, ALPHA * t.y, ALPHA * t.z, ALPHA * t.w);
}

// ---------------- final: out = (H0 + H1 + H2 + t)/4; t = 0 ------------------
__global__ void k_final(float4* __restrict__ T,
                        const __half2* __restrict__ H0,
                        const __half2* __restrict__ H1,
                        const __half2* __restrict__ H2,
                        float4* __restrict__ O, int n4)
{
    int i = blockIdx.x * blockDim.x + threadIdx.x;
    if (i >= n4) return;
    float4 t = T[i];                                  // t == e3
    float2 a01 = __half22float2(H0[2 * i]);
    float2 a23 = __half22float2(H0[2 * i + 1]);
    float2 b01 = __half22float2(H1[2 * i]);
    float2 b23 = __half22float2(H1[2 * i + 1]);
    float2 c01 = __half22float2(H2[2 * i]);
    float2 c23 = __half22float2(H2[2 * i + 1]);
    float4 o;
    o.x = (a01.x + b01.x + c01.x + t.x) * 0.25f;
    o.y = (a01.y + b01.y + c01.y + t.y) * 0.25f;
    o.z = (a23.x + b23.x + c23.x + t.z) * 0.25f;
    o.w = (a23.y + b23.y + c23.y + t.w) * 0.25f;
    O[i] = o;
    T[i] = make_float4(0.f, 0.f, 0.f, 0.f);   // restore zero-at-entry invariant
}

// ---------------------------------------------------------------------------
extern "C" void kernel_launch(void* const* d_in, const int* in_sizes, int n_in,
                              void* d_out, int out_size)
{
    const float* user_emb = (const float*)d_in[0];
    const float* item_emb = (const float*)d_in[1];
    const float* theta    = (const float*)d_in[2];
    const int*   pos_row  = (const int*)d_in[3];
    const int*   pos_col  = (const int*)d_in[4];
    const float* pos_val  = (const float*)d_in[5];
    const int*   neg_row  = (const int*)d_in[6];
    const int*   neg_col  = (const int*)d_in[7];
    const float* neg_val  = (const float*)d_in[8];
    const int*   p_row    = (const int*)d_in[9];
    const int*   p_col    = (const int*)d_in[10];
    const float* p_counts = (const float*)d_in[11];

    const int n_pos  = in_sizes[3];
    const int n_neg  = in_sizes[6];
    int n_path = in_sizes[9];
    if (n_path > MAX_EPATH) n_path = MAX_EPATH;
    const int n_theta = in_sizes[2] < 8 ? in_sizes[2] : 8;

    float *pt, *psv, *prs, *ptw;
    __half2 *hin, *h0, *h1, *h2;
    cudaGetSymbolAddress((void**)&pt,  g_t);
    cudaGetSymbolAddress((void**)&hin, g_hin);
    cudaGetSymbolAddress((void**)&h0,  g_h0);
    cudaGetSymbolAddress((void**)&h1,  g_h1);
    cudaGetSymbolAddress((void**)&h2,  g_h2);
    cudaGetSymbolAddress((void**)&psv, g_softv);
    cudaGetSymbolAddress((void**)&prs, g_rowsum);
    cudaGetSymbolAddress((void**)&ptw, g_thetaw);

    const int TB = 256;

    // fused prologue: fp16 input table + rowsum zero + theta softmax
    k_prologue<<<(NE4 + TB - 1) / TB, TB>>>((const float4*)user_emb,
                                            (const float4*)item_emb, hin,
                                            (float4*)prs, theta, ptw, n_theta);

    // path edge weights (exp + rowsums); normalization deferred to k_init
    {
        int pairs = (n_path + 1) / 2;
        k_path1<<<(pairs + TB - 1) / TB, TB>>>(p_row, p_counts, ptw, psv, prs, n_path);
    }

    // t = unnormalized path gather sums
    {
        int warps = (n_path + WEDGES - 1) / WEDGES;
        k_spmm_path<<<(warps + 7) / 8, TB>>>(p_row, p_col, psv, n_path,
                                             (const uint4*)hin, pt);
    }

    // e0 = t/rowsum; H0 = half(e0); t = a*e0
    k_init<<<(NE4 + TB - 1) / TB, TB>>>((float4*)pt, h0, prs, NE4);

    const int pos_blocks = ((n_pos + WEDGES - 1) / WEDGES + 7) / 8;
    const int neg_blocks = ((n_neg + WEDGES - 1) / WEDGES + 7) / 8;
    const int dual_grid  = pos_blocks + neg_blocks;

    // layer 1: t(=a*e0) += pos(H0) - a*neg(H0)  ->  t == e1
    k_spmm_dual<<<dual_grid, TB>>>(pos_row, pos_col, pos_val, n_pos, pos_blocks,
                                   neg_row, neg_col, neg_val, n_neg,
                                   (const uint4*)h0, pt);
    k_layer<<<(NE4 + TB - 1) / TB, TB>>>((float4*)pt, h1, NE4);

    // layer 2
    k_spmm_dual<<<dual_grid, TB>>>(pos_row, pos_col, pos_val, n_pos, pos_blocks,
                                   neg_row, neg_col, neg_val, n_neg,
                                   (const uint4*)h1, pt);
    k_layer<<<(NE4 + TB - 1) / TB, TB>>>((float4*)pt, h2, NE4);

    // layer 3 + fused final mean (t == e3 after the dual)
    k_spmm_dual<<<dual_grid, TB>>>(pos_row, pos_col, pos_val, n_pos, pos_blocks,
                                   neg_row, neg_col, neg_val, n_neg,
                                   (const uint4*)h2, pt);
    k_final<<<(NE4 + TB - 1) / TB, TB>>>((float4*)pt, h0, h1, h2,
                                         (float4*)d_out, NE4);
}